// round 3
// baseline (speedup 1.0000x reference)
#include <cuda_runtime.h>

// GetCostVolume: out[b, c2, d, h, w] with B=4, C=32, D=48, H=64, W=128
//   c2 <  32 : x[b, c2, h, w]        if w >= d else 0
//   c2 >= 32 : y[b, c2-32, h, w-d]   if w >= d else 0
//
// Store-bandwidth bound: 402.7 MB out, 8 MB in (L2-resident, 48x reuse).
// One thread per float4 of output -> coalesced STG.128.
// 3D grid: x covers (h, w4) = 2048 float4 -> 8 blocks of 256
//          y = d (48), z = b*64 + c2 (256). All decode is shift/mask.

#define B_  4
#define C_  32
#define D_  48
#define H_  64
#define W_  128
#define W4_ 32   // W/4

__global__ __launch_bounds__(256) void cost_volume_kernel(
    const float* __restrict__ x,
    const float* __restrict__ y,
    float* __restrict__ out)
{
    int hw = blockIdx.x * 256 + threadIdx.x;   // 0 .. 2047
    int w4 = hw & (W4_ - 1);
    int h  = hw >> 5;                           // 0 .. 63
    int d  = blockIdx.y;                        // 0 .. 47
    int zc = blockIdx.z;                        // b*64 + c2, 0 .. 255
    int c2 = zc & 63;
    int b  = zc >> 6;

    int w0 = w4 << 2;

    float4 v;
    if (c2 < C_) {
        // x half: aligned vector load, mask lanes where w < d
        const float* xb = x + ((((b * C_ + c2) * H_) + h) << 7);
        float4 xv = *reinterpret_cast<const float4*>(xb + w0);
        v.x = (w0 + 0 >= d) ? xv.x : 0.0f;
        v.y = (w0 + 1 >= d) ? xv.y : 0.0f;
        v.z = (w0 + 2 >= d) ? xv.z : 0.0f;
        v.w = (w0 + 3 >= d) ? xv.w : 0.0f;
    } else {
        // y half: shifted (unaligned) reads; inputs are L2-resident so cheap
        const float* yb = y + ((((b * C_ + (c2 - C_)) * H_) + h) << 7);
        v.x = (w0 + 0 >= d) ? yb[w0 + 0 - d] : 0.0f;
        v.y = (w0 + 1 >= d) ? yb[w0 + 1 - d] : 0.0f;
        v.z = (w0 + 2 >= d) ? yb[w0 + 2 - d] : 0.0f;
        v.w = (w0 + 3 >= d) ? yb[w0 + 3 - d] : 0.0f;
    }

    // out index: (((zc*48 + d)*64 + h)*32 + w4)
    long long oi = ((long long)(zc * D_ + d) << 11) + hw;
    reinterpret_cast<float4*>(out)[oi] = v;
}

extern "C" void kernel_launch(void* const* d_in, const int* in_sizes, int n_in,
                              void* d_out, int out_size)
{
    const float* x = (const float*)d_in[0];
    const float* y = (const float*)d_in[1];
    float* out = (float*)d_out;

    dim3 grid(H_ * W4_ / 256, D_, B_ * 2 * C_);  // (8, 48, 256)
    cost_volume_kernel<<<grid, 256>>>(x, y, out);
}

// round 6
// speedup vs baseline: 1.3104x; 1.3104x over previous
#include <cuda_runtime.h>

// GetCostVolume: out[b, c2, d, h, w], B=4 C=32 D=48 H=64 W=128
//   c2 <  32 : x[b, c2, h, w]        if w >= d else 0
//   c2 >= 32 : y[b, c2-32, h, w-d]   if w >= d else 0
//
// R4: one block per input row pair (b,c,h); serve all 48 d-slices from
// registers (x) + padded smem (y). Kills the ~400 MB of redundant L2 load
// traffic that was co-limiting with the 402 MB store stream.
//
// Block: 256 threads = (dj 0..7) x (w4 0..31). 6 d-iterations per thread.
// smem y row padded s[i + i/32] -> stride-4 lane reads are conflict-free.

#define D_  48

__global__ __launch_bounds__(256) void cost_volume_kernel(
    const float* __restrict__ x,
    const float* __restrict__ y,
    float* __restrict__ out)
{
    __shared__ float4 s_x[32];
    __shared__ float  s_y[132];   // 128 + padding (i + i/32, max 130)

    int t  = threadIdx.x;
    int h  = blockIdx.x;          // 0..63
    int bc = blockIdx.y;          // b*32 + c, 0..127
    int row = (bc * 64 + h) * 32; // float4 offset of this row in x/y

    // Stage inputs: warp 0 -> x row, warp 1 -> y row (padded scatter)
    if (t < 32) {
        s_x[t] = reinterpret_cast<const float4*>(x)[row + t];
    } else if (t < 64) {
        int lane = t - 32;
        float4 v = reinterpret_cast<const float4*>(y)[row + lane];
        int i = lane << 2;
        s_y[(i + 0) + ((i + 0) >> 5)] = v.x;
        s_y[(i + 1) + ((i + 1) >> 5)] = v.y;
        s_y[(i + 2) + ((i + 2) >> 5)] = v.z;
        s_y[(i + 3) + ((i + 3) >> 5)] = v.w;
    }
    __syncthreads();

    int w4 = t & 31;
    int dj = t >> 5;              // 0..7
    int w0 = w4 << 2;

    float4 xv = s_x[w4];

    int b = bc >> 5;
    int c = bc & 31;
    // float4 index bases: out[b][c2][d][h][w] -> ((bc2*48 + d)*64 + h)*32 + w4
    int basex = ((b * 64 + c) * D_) << 11;          // c2 = c
    int basey = basex + ((32 * D_) << 11);          // c2 = c + 32
    int hw = (h << 5) + w4;

    float4* outv = reinterpret_cast<float4*>(out);

#pragma unroll
    for (int k = 0; k < 6; k++) {
        int d = dj + (k << 3);    // dj, dj+8, ..., dj+40

        float4 vx;
        vx.x = (w0 + 0 >= d) ? xv.x : 0.0f;
        vx.y = (w0 + 1 >= d) ? xv.y : 0.0f;
        vx.z = (w0 + 2 >= d) ? xv.z : 0.0f;
        vx.w = (w0 + 3 >= d) ? xv.w : 0.0f;

        int i0 = w0 - d;
        float4 vy;
        vy.x = (i0 + 0 >= 0) ? s_y[(i0 + 0) + ((i0 + 0) >> 5)] : 0.0f;
        vy.y = (i0 + 1 >= 0) ? s_y[(i0 + 1) + ((i0 + 1) >> 5)] : 0.0f;
        vy.z = (i0 + 2 >= 0) ? s_y[(i0 + 2) + ((i0 + 2) >> 5)] : 0.0f;
        vy.w = (i0 + 3 >= 0) ? s_y[(i0 + 3) + ((i0 + 3) >> 5)] : 0.0f;

        int doff = (d << 11) + hw;
        outv[basex + doff] = vx;
        outv[basey + doff] = vy;
    }
}

extern "C" void kernel_launch(void* const* d_in, const int* in_sizes, int n_in,
                              void* d_out, int out_size)
{
    const float* x = (const float*)d_in[0];
    const float* y = (const float*)d_in[1];
    float* out = (float*)d_out;

    dim3 grid(64, 128);   // (h, b*32+c)
    cost_volume_kernel<<<grid, 256>>>(x, y, out);
}

// round 7
// speedup vs baseline: 1.3360x; 1.0195x over previous
#include <cuda_runtime.h>

// GetCostVolume: out[b, c2, d, h, w], B=4 C=32 D=48 H=64 W=128
//   c2 <  32 : x[b, c2, h, w]        if w >= d else 0
//   c2 >= 32 : y[b, c2-32, h, w-d]   if w >= d else 0
//
// R6: block = (b,c, h-tile of 8). Each thread owns one (h, w4) column:
//   - x float4 held in a register (gmem load, L2-hot), masked per d.
//   - y row staged in smem with a 48-float ZERO PREFIX so the shifted read
//     s_y[48 + w0 - d + j] needs NO mask/select — zeros fall out naturally.
//   - loop over all 48 d; per d the 8 warps write 8 adjacent 512B rows
//     = 4KB contiguous per half -> better L2->HBM write combining.
// Padded smem index p(i) = i + (i>>5): stride-4 lane reads conflict-free.

#define D_   48
#define SY_STRIDE 184   // p(175) = 180 max, rounded up

__global__ __launch_bounds__(256) void cost_volume_kernel(
    const float* __restrict__ x,
    const float* __restrict__ y,
    float* __restrict__ out)
{
    __shared__ float s_y[8][SY_STRIDE];

    int t  = threadIdx.x;
    int w4 = t & 31;
    int hs = t >> 5;                  // 0..7, h sub-row (= warp id)
    int ht = blockIdx.x;              // 0..7, h tile
    int bc = blockIdx.y;              // b*32 + c, 0..127
    int h  = (ht << 3) + hs;          // 0..63

    int rowv = (bc * 64 + h) * 32;    // float4 offset of this (b,c,h) row

    // Zero prefix: i in [0,48) for all 8 rows (384 slots, padded positions)
    for (int idx = t; idx < 8 * 48; idx += 256) {
        int r = idx / 48, i = idx - r * 48;
        s_y[r][i + (i >> 5)] = 0.0f;
    }

    // Stage y row (each thread scatters its float4 into padded slots 48+)
    {
        float4 v = reinterpret_cast<const float4*>(y)[rowv + w4];
        int i = 48 + (w4 << 2);
        s_y[hs][(i + 0) + ((i + 0) >> 5)] = v.x;
        s_y[hs][(i + 1) + ((i + 1) >> 5)] = v.y;
        s_y[hs][(i + 2) + ((i + 2) >> 5)] = v.z;
        s_y[hs][(i + 3) + ((i + 3) >> 5)] = v.w;
    }

    // x float4 lives in registers for all 48 iterations
    float4 xv = reinterpret_cast<const float4*>(x)[rowv + w4];

    __syncthreads();

    int w0 = w4 << 2;
    int b  = bc >> 5;
    int c  = bc & 31;
    int hw = (h << 5) + w4;                       // (h, w4) within a d-slice
    int basex = ((b * 64 + c) * D_) * 2048 + hw;  // float4 units, c2 = c
    int basey = basex + 32 * D_ * 2048;           // c2 = c + 32

    float4* outv = reinterpret_cast<float4*>(out);
    const float* yr = s_y[hs];

#pragma unroll
    for (int d = 0; d < D_; d++) {
        float4 vx;
        vx.x = (w0 + 0 >= d) ? xv.x : 0.0f;
        vx.y = (w0 + 1 >= d) ? xv.y : 0.0f;
        vx.z = (w0 + 2 >= d) ? xv.z : 0.0f;
        vx.w = (w0 + 3 >= d) ? xv.w : 0.0f;

        int i0 = 48 + w0 - d;                     // always >= 1
        float4 vy;
        vy.x = yr[(i0 + 0) + ((i0 + 0) >> 5)];
        vy.y = yr[(i0 + 1) + ((i0 + 1) >> 5)];
        vy.z = yr[(i0 + 2) + ((i0 + 2) >> 5)];
        vy.w = yr[(i0 + 3) + ((i0 + 3) >> 5)];

        int doff = d << 11;                       // d * 2048 float4s
        outv[basex + doff] = vx;
        outv[basey + doff] = vy;
    }
}

extern "C" void kernel_launch(void* const* d_in, const int* in_sizes, int n_in,
                              void* d_out, int out_size)
{
    const float* x = (const float*)d_in[0];
    const float* y = (const float*)d_in[1];
    float* out = (float*)d_out;

    dim3 grid(8, 128);   // (h tile, b*32+c)
    cost_volume_kernel<<<grid, 256>>>(x, y, out);
}